// round 3
// baseline (speedup 1.0000x reference)
#include <cuda_runtime.h>

// x: (B=64, NU=32, IC=256, UNIT=128) fp32, contiguous.
// Reference reinterprets flat buffer as (B, IC, NU, UNIT):
//   u_hat[b,i,j,u] = x_flat[b*1048576 + i*4096 + j*128 + u]
// s[b,j,u] = (1/256) * sum_i u_hat[b,i,j,u]; then squash over u (128 elems).
// Output: (B, NU, UNIT) = 262144 fp32.
//
// R3: persistent grid = 148 SMs * 8 blocks = 1184 blocks (one full wave,
// 9472 resident warps). Each block grid-strides over the 2048 (b,j) groups,
// eliminating the round-2 two-wave tail (wave 2 was only 73% filled).
// Per group: warp w sums i-rows [w*32, w*32+32), lane l owns float4 u=4l.
// __ldcs streaming loads (read-once data). Smem combine + warp-0 squash.

static constexpr int IC       = 256;
static constexpr int GROUPS   = 64 * 32;        // 2048
static constexpr int STRIDE4  = 4096 / 4;       // i-stride in float4 units
static constexpr int THREADS  = 256;            // 8 warps/block
static constexpr int IC_PER_W = IC / 8;         // 32 rows per warp
static constexpr int BLOCKS   = 148 * 8;        // 1184: one full wave

__global__ __launch_bounds__(THREADS, 8)
void capsule_squash_kernel(const float4* __restrict__ x4,
                           float4* __restrict__ out4) {
    const int warp = threadIdx.x >> 5;
    const int lane = threadIdx.x & 31;

    __shared__ float4 part[8][32];

    for (int g = blockIdx.x; g < GROUPS; g += BLOCKS) {
        const int b = g >> 5;
        const int j = g & 31;
        const int base4 = b * (1048576 / 4) + j * (128 / 4) + lane
                        + (warp * IC_PER_W) * STRIDE4;

        float4 s = make_float4(0.f, 0.f, 0.f, 0.f);
#pragma unroll 8
        for (int i = 0; i < IC_PER_W; i++) {
            float4 v = __ldcs(&x4[base4 + i * STRIDE4]);
            s.x += v.x; s.y += v.y; s.z += v.z; s.w += v.w;
        }

        part[warp][lane] = s;
        __syncthreads();

        if (warp == 0) {
            float4 t = part[0][lane];
#pragma unroll
            for (int w = 1; w < 8; w++) {
                float4 p = part[w][lane];
                t.x += p.x; t.y += p.y; t.z += p.z; t.w += p.w;
            }
            const float c = 1.0f / 256.0f;
            t.x *= c; t.y *= c; t.z *= c; t.w *= c;

            float sq = t.x * t.x + t.y * t.y + t.z * t.z + t.w * t.w;
#pragma unroll
            for (int off = 16; off > 0; off >>= 1)
                sq += __shfl_xor_sync(0xffffffffu, sq, off);

            const float mag   = sqrtf(sq);
            const float scale = sq / (1.0f + sq) / (mag + 1e-5f);

            out4[g * 32 + lane] = make_float4(t.x * scale, t.y * scale,
                                              t.z * scale, t.w * scale);
        }
        __syncthreads();   // protect smem reuse across grid-stride iterations
    }
}

extern "C" void kernel_launch(void* const* d_in, const int* in_sizes, int n_in,
                              void* d_out, int out_size) {
    const float4* x4 = (const float4*)d_in[0];
    float4* out4 = (float4*)d_out;
    capsule_squash_kernel<<<BLOCKS, THREADS>>>(x4, out4);
}

// round 4
// speedup vs baseline: 1.0887x; 1.0887x over previous
#include <cuda_runtime.h>

// x: (B=64, NU=32, IC=256, UNIT=128) fp32, contiguous.
// Reference reinterprets flat buffer as (B, IC, NU, UNIT):
//   u_hat[b,i,j,u] = x_flat[b*1048576 + i*4096 + j*128 + u]
// s[b,j,u] = (1/256) * sum_i u_hat[b,i,j,u]; then squash over u (128 elems).
// Output: (B, NU, UNIT) = 262144 fp32.
//
// R4: one 128-thread block (4 warps) per (b,j) group -> 2048 blocks.
// At <=32 regs, 14+ blocks fit per SM, so ALL 2048 blocks are co-resident
// in a single wave (2048/148 = 13.8/SM): no wave-quantization tail (R2's
// 2-wave deficit) and no intra-block serialization (R3's persistent-loop
// regression). Warp w sums i-rows [w*64, w*64+64); lane l owns float4 u=4l.
// Smem combine across 4 warps; warp 0 squashes + stores.

static constexpr int IC       = 256;
static constexpr int GROUPS   = 64 * 32;        // 2048 blocks
static constexpr int STRIDE4  = 4096 / 4;       // i-stride in float4 units
static constexpr int THREADS  = 128;            // 4 warps/block
static constexpr int IC_PER_W = IC / 4;         // 64 rows per warp

__global__ __launch_bounds__(THREADS, 14)
void capsule_squash_kernel(const float4* __restrict__ x4,
                           float4* __restrict__ out4) {
    const int g    = blockIdx.x;                // group = b*32 + j
    const int warp = threadIdx.x >> 5;
    const int lane = threadIdx.x & 31;

    const int b = g >> 5;
    const int j = g & 31;
    const int base4 = b * (1048576 / 4) + j * (128 / 4) + lane
                    + (warp * IC_PER_W) * STRIDE4;

    float4 s = make_float4(0.f, 0.f, 0.f, 0.f);
#pragma unroll 8
    for (int i = 0; i < IC_PER_W; i++) {
        float4 v = __ldg(&x4[base4 + i * STRIDE4]);
        s.x += v.x; s.y += v.y; s.z += v.z; s.w += v.w;
    }

    __shared__ float4 part[4][32];
    part[warp][lane] = s;
    __syncthreads();

    if (warp == 0) {
        float4 t = part[0][lane];
#pragma unroll
        for (int w = 1; w < 4; w++) {
            float4 p = part[w][lane];
            t.x += p.x; t.y += p.y; t.z += p.z; t.w += p.w;
        }
        const float c = 1.0f / 256.0f;
        t.x *= c; t.y *= c; t.z *= c; t.w *= c;

        // mag_sq over the 128-element unit dim (warp-wide)
        float sq = t.x * t.x + t.y * t.y + t.z * t.z + t.w * t.w;
#pragma unroll
        for (int off = 16; off > 0; off >>= 1)
            sq += __shfl_xor_sync(0xffffffffu, sq, off);

        const float mag   = sqrtf(sq);
        const float scale = sq / (1.0f + sq) / (mag + 1e-5f);

        out4[g * 32 + lane] = make_float4(t.x * scale, t.y * scale,
                                          t.z * scale, t.w * scale);
    }
}

extern "C" void kernel_launch(void* const* d_in, const int* in_sizes, int n_in,
                              void* d_out, int out_size) {
    const float4* x4 = (const float4*)d_in[0];
    float4* out4 = (float4*)d_out;
    capsule_squash_kernel<<<GROUPS, THREADS>>>(x4, out4);
}

// round 5
// speedup vs baseline: 1.1229x; 1.0315x over previous
#include <cuda_runtime.h>

// x: (B=64, NU=32, IC=256, UNIT=128) fp32, contiguous.
// Reference reinterprets flat buffer as (B, IC, NU, UNIT):
//   u_hat[b,i,j,u] = x_flat[b*1048576 + i*4096 + j*128 + u]
// s[b,j,u] = (1/256) * sum_i u_hat[b,i,j,u]; then squash over u (128 elems).
// Output: (B, NU, UNIT) = 262144 fp32.
//
// R5: R4 structure (one 128-thread block per (b,j), 2048 blocks, one wave)
// with i INTERLEAVED across warps (i = warp + 4k): the block's 4 warps read
// 4 consecutive 16KB rows at the same 512B column -> dense 64KB live window
// (vs 4 points spread over 1MB in R4) for HBM row-buffer locality.
// __ldcs streaming (read-once), unroll 16 for deeper MLP.

static constexpr int IC       = 256;
static constexpr int GROUPS   = 64 * 32;        // 2048 blocks
static constexpr int STRIDE4  = 4096 / 4;       // i-stride in float4 units
static constexpr int THREADS  = 128;            // 4 warps/block
static constexpr int IC_PER_W = IC / 4;         // 64 rows per warp

__global__ __launch_bounds__(THREADS, 16)
void capsule_squash_kernel(const float4* __restrict__ x4,
                           float4* __restrict__ out4) {
    const int g    = blockIdx.x;                // group = b*32 + j
    const int warp = threadIdx.x >> 5;
    const int lane = threadIdx.x & 31;

    const int b = g >> 5;
    const int j = g & 31;
    // warp w reads rows i = w, w+4, w+8, ... (interleaved, not blocked)
    const int base4 = b * (1048576 / 4) + j * (128 / 4) + lane
                    + warp * STRIDE4;

    float4 s = make_float4(0.f, 0.f, 0.f, 0.f);
#pragma unroll 16
    for (int k = 0; k < IC_PER_W; k++) {
        float4 v = __ldcs(&x4[base4 + k * (4 * STRIDE4)]);
        s.x += v.x; s.y += v.y; s.z += v.z; s.w += v.w;
    }

    __shared__ float4 part[4][32];
    part[warp][lane] = s;
    __syncthreads();

    if (warp == 0) {
        float4 t = part[0][lane];
#pragma unroll
        for (int w = 1; w < 4; w++) {
            float4 p = part[w][lane];
            t.x += p.x; t.y += p.y; t.z += p.z; t.w += p.w;
        }
        const float c = 1.0f / 256.0f;
        t.x *= c; t.y *= c; t.z *= c; t.w *= c;

        // mag_sq over the 128-element unit dim (warp-wide)
        float sq = t.x * t.x + t.y * t.y + t.z * t.z + t.w * t.w;
#pragma unroll
        for (int off = 16; off > 0; off >>= 1)
            sq += __shfl_xor_sync(0xffffffffu, sq, off);

        const float mag   = sqrtf(sq);
        const float scale = sq / (1.0f + sq) / (mag + 1e-5f);

        out4[g * 32 + lane] = make_float4(t.x * scale, t.y * scale,
                                          t.z * scale, t.w * scale);
    }
}

extern "C" void kernel_launch(void* const* d_in, const int* in_sizes, int n_in,
                              void* d_out, int out_size) {
    const float4* x4 = (const float4*)d_in[0];
    float4* out4 = (float4*)d_out;
    capsule_squash_kernel<<<GROUPS, THREADS>>>(x4, out4);
}